// round 2
// baseline (speedup 1.0000x reference)
#include <cuda_runtime.h>
#include <cuda_bf16.h>
#include <math.h>

// Problem constants
#define B_ 8
#define S_ 8192
#define D_ 512
#define C_ 512
#define H_ 8
#define HD_ 64
#define L_ 2
#define DFF_ 2048
#define M_ (B_ * C_)          // 4096 rows for all projection GEMMs
#define QKV3D (3 * D_)        // 1536

// ------------------------- scratch (device globals) -------------------------
__device__ float g_x[M_ * D_];        // chunk states [B*C, D]
__device__ float g_qkv[M_ * QKV3D];   // qkv proj     [B*C, 3D]
__device__ float g_attno[M_ * D_];    // attention out
__device__ float g_proj[M_ * D_];     // proj / ff2 result
__device__ float g_ff[M_ * DFF_];     // ff1 result
__device__ float g_y[M_ * D_];        // final-LN'd chunks

// ------------------------------- pooling ------------------------------------
// One block per (c, b). segment_ids sorted per batch -> binary search bounds.
__global__ void pool_kernel(const float* __restrict__ tokens,
                            const int* __restrict__ seg,
                            float* __restrict__ x) {
    int c = blockIdx.x;
    int b = blockIdx.y;
    const int* ids = seg + (size_t)b * S_;
    // lower_bound(c), lower_bound(c+1)
    int lo = 0, hi = S_;
    while (lo < hi) { int mid = (lo + hi) >> 1; if (ids[mid] < c) lo = mid + 1; else hi = mid; }
    int s0 = lo;
    hi = S_;
    while (lo < hi) { int mid = (lo + hi) >> 1; if (ids[mid] < c + 1) lo = mid + 1; else hi = mid; }
    int s1 = lo;
    float inv = 1.0f / (float)(s1 - s0);

    int d = threadIdx.x;              // 256 threads, 2 dims each
    float sum0 = 0.f, sum1 = 0.f;
    for (int s = s0; s < s1; s++) {
        const float* t = tokens + ((size_t)b * S_ + s) * D_;
        sum0 += t[d];
        sum1 += t[d + 256];
    }
    float* xr = x + ((size_t)b * C_ + c) * D_;
    xr[d]       = sum0 * inv;
    xr[d + 256] = sum1 * inv;
}

// ------------------------------- GEMM ---------------------------------------
// Y[M,N] = X[M,K] @ W[N,K]^T + bias[N], optional relu.
// Tile 128x64, BK=16, 256 threads, 8x4 per thread.
__global__ void gemm_kernel(const float* __restrict__ X,
                            const float* __restrict__ W,
                            const float* __restrict__ bias,
                            float* __restrict__ Y,
                            int M, int N, int K, int relu) {
    __shared__ float Xs[16][132];   // [k][row], pad 4
    __shared__ float Ws[16][68];    // [k][col], pad 4

    int tid = threadIdx.x;
    int tx = tid & 15;              // N dir (4 cols)
    int ty = tid >> 4;              // M dir (8 rows)
    int row0 = blockIdx.y * 128;
    int col0 = blockIdx.x * 64;

    float acc[8][4];
#pragma unroll
    for (int i = 0; i < 8; i++)
#pragma unroll
        for (int j = 0; j < 4; j++) acc[i][j] = 0.f;

    for (int k0 = 0; k0 < K; k0 += 16) {
        // X tile: 128 rows x 16 k = 512 float4 -> 2 per thread
#pragma unroll
        for (int t = 0; t < 2; t++) {
            int lin = tid + t * 256;
            int r = lin >> 2;
            int kq = (lin & 3) * 4;
            float4 v = *(const float4*)(X + (size_t)(row0 + r) * K + k0 + kq);
            Xs[kq + 0][r] = v.x; Xs[kq + 1][r] = v.y;
            Xs[kq + 2][r] = v.z; Xs[kq + 3][r] = v.w;
        }
        // W tile: 64 rows x 16 k = 256 float4 -> 1 per thread
        {
            int r = tid >> 2;
            int kq = (tid & 3) * 4;
            float4 v = *(const float4*)(W + (size_t)(col0 + r) * K + k0 + kq);
            Ws[kq + 0][r] = v.x; Ws[kq + 1][r] = v.y;
            Ws[kq + 2][r] = v.z; Ws[kq + 3][r] = v.w;
        }
        __syncthreads();
#pragma unroll
        for (int kk = 0; kk < 16; kk++) {
            float4 a0 = *(const float4*)&Xs[kk][ty * 8];
            float4 a1 = *(const float4*)&Xs[kk][ty * 8 + 4];
            float4 bb = *(const float4*)&Ws[kk][tx * 4];
            float a[8] = {a0.x, a0.y, a0.z, a0.w, a1.x, a1.y, a1.z, a1.w};
            float bj[4] = {bb.x, bb.y, bb.z, bb.w};
#pragma unroll
            for (int i = 0; i < 8; i++)
#pragma unroll
                for (int j = 0; j < 4; j++) acc[i][j] += a[i] * bj[j];
        }
        __syncthreads();
    }

    float b0 = bias[col0 + tx * 4 + 0];
    float b1 = bias[col0 + tx * 4 + 1];
    float b2 = bias[col0 + tx * 4 + 2];
    float b3 = bias[col0 + tx * 4 + 3];
#pragma unroll
    for (int i = 0; i < 8; i++) {
        int row = row0 + ty * 8 + i;
        float4 r4;
        r4.x = acc[i][0] + b0; r4.y = acc[i][1] + b1;
        r4.z = acc[i][2] + b2; r4.w = acc[i][3] + b3;
        if (relu) {
            r4.x = fmaxf(r4.x, 0.f); r4.y = fmaxf(r4.y, 0.f);
            r4.z = fmaxf(r4.z, 0.f); r4.w = fmaxf(r4.w, 0.f);
        }
        *(float4*)(Y + (size_t)row * N + col0 + tx * 4) = r4;
    }
}

// ------------------------------ attention -----------------------------------
// Flash-style: block = (q-tile of 32 rows, b*H+h). 256 threads (16x16),
// thread owns 2 rows x 4 cols. Online softmax over 8 key tiles of 64.
__global__ void attn_kernel(const float* __restrict__ qkv,
                            float* __restrict__ o) {
    int qt = blockIdx.x;            // 0..15
    int bh = blockIdx.y;            // 0..63
    int b = bh >> 3;
    int h = bh & 7;
    const float* baseQ = qkv + (size_t)b * C_ * QKV3D + h * HD_;
    const float* baseK = baseQ + D_;
    const float* baseV = baseQ + 2 * D_;

    __shared__ float Qs[64][36];    // [dd][row] (32 rows used)
    __shared__ float KP[64][68];    // Ks [dd][key]; aliased as Ps[key*36+row]
    __shared__ float Vs[64][64];    // [key][dim]

    int tid = threadIdx.x;
    int tx = tid & 15;              // key/dim dir, 4 each
    int ty = tid >> 4;              // row dir, 2 each
    int row0 = qt * 32;

    // load Q transposed: 32 rows x 64 dd = 512 float4 -> 2 per thread
#pragma unroll
    for (int t = 0; t < 2; t++) {
        int lin = tid + t * 256;
        int r = lin >> 4;                 // 0..31
        int dq = (lin & 15) * 4;          // 0..60
        float4 v = *(const float4*)(baseQ + (size_t)(row0 + r) * QKV3D + dq);
        Qs[dq + 0][r] = v.x; Qs[dq + 1][r] = v.y;
        Qs[dq + 2][r] = v.z; Qs[dq + 3][r] = v.w;
    }

    float m[2] = {-1e30f, -1e30f};
    float l[2] = {0.f, 0.f};
    float O[2][4];
#pragma unroll
    for (int i = 0; i < 2; i++)
#pragma unroll
        for (int j = 0; j < 4; j++) O[i][j] = 0.f;

    for (int kt = 0; kt < 8; kt++) {
        int k0 = kt * 64;
        // load K transposed + V natural: each 1024 float4 -> 4 per thread
#pragma unroll
        for (int t = 0; t < 4; t++) {
            int lin = tid + t * 256;
            int key = lin >> 4;
            int dq = (lin & 15) * 4;
            float4 vk = *(const float4*)(baseK + (size_t)(k0 + key) * QKV3D + dq);
            KP[dq + 0][key] = vk.x; KP[dq + 1][key] = vk.y;
            KP[dq + 2][key] = vk.z; KP[dq + 3][key] = vk.w;
            float4 vv = *(const float4*)(baseV + (size_t)(k0 + key) * QKV3D + dq);
            *(float4*)&Vs[key][dq] = vv;
        }
        __syncthreads();

        // S = Q K^T * scale
        float s[2][4] = {{0.f,0.f,0.f,0.f},{0.f,0.f,0.f,0.f}};
#pragma unroll
        for (int kk = 0; kk < 64; kk++) {
            float a0 = Qs[kk][ty * 2 + 0];
            float a1 = Qs[kk][ty * 2 + 1];
            float4 bb = *(const float4*)&KP[kk][tx * 4];
            s[0][0] += a0 * bb.x; s[0][1] += a0 * bb.y;
            s[0][2] += a0 * bb.z; s[0][3] += a0 * bb.w;
            s[1][0] += a1 * bb.x; s[1][1] += a1 * bb.y;
            s[1][2] += a1 * bb.z; s[1][3] += a1 * bb.w;
        }
        float p[2][4];
#pragma unroll
        for (int i = 0; i < 2; i++) {
            float tm = -1e30f;
#pragma unroll
            for (int j = 0; j < 4; j++) { s[i][j] *= 0.125f; tm = fmaxf(tm, s[i][j]); }
#pragma unroll
            for (int off = 1; off < 16; off <<= 1)
                tm = fmaxf(tm, __shfl_xor_sync(0xffffffffu, tm, off));
            float mn = fmaxf(m[i], tm);
            float alpha = __expf(m[i] - mn);
            float ps = 0.f;
#pragma unroll
            for (int j = 0; j < 4; j++) { p[i][j] = __expf(s[i][j] - mn); ps += p[i][j]; }
#pragma unroll
            for (int off = 1; off < 16; off <<= 1)
                ps += __shfl_xor_sync(0xffffffffu, ps, off);
            l[i] = l[i] * alpha + ps;
            m[i] = mn;
#pragma unroll
            for (int j = 0; j < 4; j++) O[i][j] *= alpha;
        }
        __syncthreads();   // everyone done reading KP as K
        // stage P into KP region as Ps[key*36 + row]
        float* Ps = &KP[0][0];
#pragma unroll
        for (int i = 0; i < 2; i++)
#pragma unroll
            for (int j = 0; j < 4; j++)
                Ps[(tx * 4 + j) * 36 + ty * 2 + i] = p[i][j];
        __syncthreads();
        // O += P V
#pragma unroll
        for (int kk = 0; kk < 64; kk++) {
            float a0 = Ps[kk * 36 + ty * 2 + 0];
            float a1 = Ps[kk * 36 + ty * 2 + 1];
            float4 bb = *(const float4*)&Vs[kk][tx * 4];
            O[0][0] += a0 * bb.x; O[0][1] += a0 * bb.y;
            O[0][2] += a0 * bb.z; O[0][3] += a0 * bb.w;
            O[1][0] += a1 * bb.x; O[1][1] += a1 * bb.y;
            O[1][2] += a1 * bb.z; O[1][3] += a1 * bb.w;
        }
        __syncthreads();   // before next tile overwrites KP/Vs
    }

#pragma unroll
    for (int i = 0; i < 2; i++) {
        float inv = 1.0f / l[i];
        int row = row0 + ty * 2 + i;
        float4 r4 = make_float4(O[i][0] * inv, O[i][1] * inv,
                                O[i][2] * inv, O[i][3] * inv);
        *(float4*)(o + ((size_t)b * C_ + row) * D_ + h * HD_ + tx * 4) = r4;
    }
}

// -------------------------- residual + layernorm ----------------------------
// out[row] = LN(xin[row] + res[row]) * w + b   (res may be null)
__global__ void ln_kernel(const float* __restrict__ xin,
                          const float* __restrict__ res,
                          const float* __restrict__ w,
                          const float* __restrict__ bv,
                          float* __restrict__ out) {
    int row = blockIdx.x;
    int tid = threadIdx.x;          // 256
    size_t off = (size_t)row * D_;
    float v0 = xin[off + tid];
    float v1 = xin[off + tid + 256];
    if (res) { v0 += res[off + tid]; v1 += res[off + tid + 256]; }

    __shared__ float red[8];
    __shared__ float sbc;
    int lane = tid & 31, warp = tid >> 5;

    float s = v0 + v1;
#pragma unroll
    for (int o2 = 16; o2 >= 1; o2 >>= 1) s += __shfl_xor_sync(0xffffffffu, s, o2);
    if (lane == 0) red[warp] = s;
    __syncthreads();
    if (tid == 0) {
        float t = 0.f;
#pragma unroll
        for (int i = 0; i < 8; i++) t += red[i];
        sbc = t * (1.0f / D_);
    }
    __syncthreads();
    float mu = sbc;
    float d0 = v0 - mu, d1 = v1 - mu;
    s = d0 * d0 + d1 * d1;
    __syncthreads();                 // red reuse safety
#pragma unroll
    for (int o2 = 16; o2 >= 1; o2 >>= 1) s += __shfl_xor_sync(0xffffffffu, s, o2);
    if (lane == 0) red[warp] = s;
    __syncthreads();
    if (tid == 0) {
        float t = 0.f;
#pragma unroll
        for (int i = 0; i < 8; i++) t += red[i];
        sbc = rsqrtf(t * (1.0f / D_) + 1e-5f);
    }
    __syncthreads();
    float inv = sbc;
    out[off + tid]       = d0 * inv * w[tid] + bv[tid];
    out[off + tid + 256] = d1 * inv * w[tid + 256] + bv[tid + 256];
}

// ------------------------------- expand -------------------------------------
__global__ void expand_kernel(const float* __restrict__ y,
                              const int* __restrict__ seg,
                              float* __restrict__ out) {
    int bs = blockIdx.x;            // 0..B*S-1
    int b = bs >> 13;
    int c = seg[bs];
    const float4* src = (const float4*)(y + ((size_t)b * C_ + c) * D_);
    float4* dst = (float4*)(out + (size_t)bs * D_);
    dst[threadIdx.x] = src[threadIdx.x];   // 128 threads x float4 = 512 floats
}

// ------------------------------ launcher ------------------------------------
extern "C" void kernel_launch(void* const* d_in, const int* in_sizes, int n_in,
                              void* d_out, int out_size) {
    const float* tokens = (const float*)d_in[0];
    const int*   seg    = (const int*)d_in[1];
    const float* qkv_w  = (const float*)d_in[2];
    const float* qkv_b  = (const float*)d_in[3];
    const float* out_w  = (const float*)d_in[4];
    const float* out_b  = (const float*)d_in[5];
    const float* ln1_w  = (const float*)d_in[6];
    const float* ln1_b  = (const float*)d_in[7];
    const float* ln2_w  = (const float*)d_in[8];
    const float* ln2_b  = (const float*)d_in[9];
    const float* ff1_w  = (const float*)d_in[10];
    const float* ff1_b  = (const float*)d_in[11];
    const float* ff2_w  = (const float*)d_in[12];
    const float* ff2_b  = (const float*)d_in[13];
    const float* fln_w  = (const float*)d_in[14];
    const float* fln_b  = (const float*)d_in[15];
    float* out = (float*)d_out;

    float *x, *qkv, *attno, *proj, *ff, *y;
    cudaGetSymbolAddress((void**)&x, g_x);
    cudaGetSymbolAddress((void**)&qkv, g_qkv);
    cudaGetSymbolAddress((void**)&attno, g_attno);
    cudaGetSymbolAddress((void**)&proj, g_proj);
    cudaGetSymbolAddress((void**)&ff, g_ff);
    cudaGetSymbolAddress((void**)&y, g_y);

    pool_kernel<<<dim3(C_, B_), 256>>>(tokens, seg, x);

    for (int l = 0; l < L_; l++) {
        const float* qw = qkv_w + (size_t)l * QKV3D * D_;
        const float* qb = qkv_b + (size_t)l * QKV3D;
        const float* ow = out_w + (size_t)l * D_ * D_;
        const float* ob = out_b + (size_t)l * D_;
        const float* f1w = ff1_w + (size_t)l * DFF_ * D_;
        const float* f1b = ff1_b + (size_t)l * DFF_;
        const float* f2w = ff2_w + (size_t)l * D_ * DFF_;
        const float* f2b = ff2_b + (size_t)l * D_;

        gemm_kernel<<<dim3(QKV3D / 64, M_ / 128), 256>>>(x, qw, qb, qkv, M_, QKV3D, D_, 0);
        attn_kernel<<<dim3(C_ / 32, B_ * H_), 256>>>(qkv, attno);
        gemm_kernel<<<dim3(D_ / 64, M_ / 128), 256>>>(attno, ow, ob, proj, M_, D_, D_, 0);
        ln_kernel<<<M_, 256>>>(x, proj, ln1_w + (size_t)l * D_, ln1_b + (size_t)l * D_, x);
        gemm_kernel<<<dim3(DFF_ / 64, M_ / 128), 256>>>(x, f1w, f1b, ff, M_, DFF_, D_, 1);
        gemm_kernel<<<dim3(D_ / 64, M_ / 128), 256>>>(ff, f2w, f2b, proj, M_, D_, DFF_, 0);
        ln_kernel<<<M_, 256>>>(x, proj, ln2_w + (size_t)l * D_, ln2_b + (size_t)l * D_, x);
    }

    ln_kernel<<<M_, 256>>>(x, nullptr, fln_w, fln_b, y);
    expand_kernel<<<B_ * S_, 128>>>(y, seg, out);
}

// round 4
// speedup vs baseline: 1.6610x; 1.6610x over previous
#include <cuda_runtime.h>
#include <cuda_bf16.h>
#include <mma.h>
#include <math.h>
#include <stdint.h>

using namespace nvcuda;

// Problem constants
#define B_ 8
#define S_ 8192
#define D_ 512
#define C_ 512
#define H_ 8
#define HD_ 64
#define L_ 2
#define DFF_ 2048
#define M_ (B_ * C_)          // 4096
#define QKV3D (3 * D_)        // 1536

// ------------------------- scratch (device globals) -------------------------
__device__ float g_x[M_ * D_];
__device__ float g_qkv[M_ * QKV3D];
__device__ float g_attno[M_ * D_];
__device__ float g_proj[M_ * D_];
__device__ float g_ff[M_ * DFF_];
__device__ float g_y[M_ * D_];
__device__ float g_scores[B_ * H_ * C_ * C_];

__device__ __forceinline__ void cvt_hilo(float x, __nv_bfloat16& h, __nv_bfloat16& l) {
    h = __float2bfloat16(x);
    l = __float2bfloat16(x - __bfloat162float(h));
}

// ----------------------- tensor-core GEMM (WMMA bf16 hi/lo) -------------------
// C[M,N] = A[M,K] @ B + bias, fp32 in/out. Split each fp32 into bf16 hi+lo,
// compute Ah*Bh + Ah*Bl + Al*Bh on HMMA. Tile BM=128, BN=64, fp32 K-chunk 32.
//   flags bit1==0 : B_mem[n][k]  (weights W[N,K] / K rows of keys)
//   flags bit1==1 : B_mem[k][n]  (V)
//   flags bit0    : relu
// Batch z: off = (z>>3)*s_hi + (z&7)*s_lo per tensor.
#define LDA_S 72   // smem row stride in bf16 elems: 32 hi + 32 lo + 8 pad

__global__ void __launch_bounds__(256)
gemm_mma(const float* __restrict__ A, const float* __restrict__ Bm,
         const float* __restrict__ bias, float* __restrict__ Cm,
         int K, int lda, int ldb, int ldc,
         long long sAhi, long long sAlo, long long sBhi, long long sBlo,
         long long sChi, long long sClo, int flags)
{
    __shared__ alignas(16) __nv_bfloat16 As[128 * LDA_S];   // 18432 B
    __shared__ alignas(16) __nv_bfloat16 Bs[64 * LDA_S];    //  9216 B
    __shared__ float biass[64];
    float* Cs = reinterpret_cast<float*>(As);               // 128x36 fp32 overlay

    const int tid = threadIdx.x;
    const int wid = tid >> 5;
    const int warp_m = wid & 3;        // 0..3  -> 32-row band
    const int warp_n = wid >> 2;       // 0..1  -> 32-col band
    const int z = blockIdx.z;
    const long long offA = (long long)(z >> 3) * sAhi + (long long)(z & 7) * sAlo;
    const long long offB = (long long)(z >> 3) * sBhi + (long long)(z & 7) * sBlo;
    const long long offC = (long long)(z >> 3) * sChi + (long long)(z & 7) * sClo;
    const int row0 = blockIdx.y * 128;
    const int n0 = blockIdx.x * 64;
    const float* Ab = A + offA + (long long)row0 * lda;
    const float* Bb = Bm + offB;
    const int kn = flags & 2;

    if (tid < 64) biass[tid] = bias ? bias[n0 + tid] : 0.f;

    wmma::fragment<wmma::accumulator, 16, 16, 16, float> acc[2][2];
#pragma unroll
    for (int i = 0; i < 2; i++)
#pragma unroll
        for (int j = 0; j < 2; j++) wmma::fill_fragment(acc[i][j], 0.f);

    const int nchunks = K >> 5;
    for (int ck = 0; ck < nchunks; ck++) {
        const int k0 = ck << 5;
        __syncthreads();   // previous iteration's compute done before restage
        // ---- A tile: 128 rows x 32 fp32 -> hi at [0,32), lo at [32,64) ----
#pragma unroll
        for (int t = 0; t < 4; t++) {
            int lin = tid + (t << 8);
            int r = lin >> 3;
            int kq = (lin & 7) << 2;
            float4 v = *(const float4*)(Ab + (long long)r * lda + k0 + kq);
            __nv_bfloat16 h0, h1, h2, h3, l0, l1, l2, l3;
            cvt_hilo(v.x, h0, l0); cvt_hilo(v.y, h1, l1);
            cvt_hilo(v.z, h2, l2); cvt_hilo(v.w, h3, l3);
            __nv_bfloat16* p = As + r * LDA_S + kq;
            p[0] = h0; p[1] = h1; p[2] = h2; p[3] = h3;
            p[32] = l0; p[33] = l1; p[34] = l2; p[35] = l3;
        }
        // ---- B tile: 64 n x 32 fp32 ----
        if (!kn) {
#pragma unroll
            for (int t = 0; t < 2; t++) {
                int lin = tid + (t << 8);
                int r = lin >> 3;
                int kq = (lin & 7) << 2;
                float4 v = *(const float4*)(Bb + (long long)(n0 + r) * ldb + k0 + kq);
                __nv_bfloat16 h0, h1, h2, h3, l0, l1, l2, l3;
                cvt_hilo(v.x, h0, l0); cvt_hilo(v.y, h1, l1);
                cvt_hilo(v.z, h2, l2); cvt_hilo(v.w, h3, l3);
                __nv_bfloat16* p = Bs + r * LDA_S + kq;
                p[0] = h0; p[1] = h1; p[2] = h2; p[3] = h3;
                p[32] = l0; p[33] = l1; p[34] = l2; p[35] = l3;
            }
        } else {
            // B_mem[k][n] -> transpose into Bs[n][k]
#pragma unroll
            for (int t = 0; t < 2; t++) {
                int lin = tid + (t << 8);
                int k = lin >> 4;              // 0..31
                int nq = (lin & 15) << 2;      // 0..60
                float4 v = *(const float4*)(Bb + (long long)(k0 + k) * ldb + n0 + nq);
                float vv[4] = {v.x, v.y, v.z, v.w};
#pragma unroll
                for (int j = 0; j < 4; j++) {
                    __nv_bfloat16 h, l;
                    cvt_hilo(vv[j], h, l);
                    Bs[(nq + j) * LDA_S + k]      = h;
                    Bs[(nq + j) * LDA_S + 32 + k] = l;
                }
            }
        }
        __syncthreads();

        // ---- compute: 2 k16-steps x {Ah*Bh, Ah*Bl, Al*Bh} ----
        const __nv_bfloat16* Abase = As + (warp_m * 32) * LDA_S;
        const __nv_bfloat16* Bbase = Bs + (warp_n * 32) * LDA_S;
#pragma unroll
        for (int ks = 0; ks < 32; ks += 16) {
            wmma::fragment<wmma::matrix_a, 16, 16, 16, __nv_bfloat16, wmma::row_major> ah[2], al[2];
            wmma::fragment<wmma::matrix_b, 16, 16, 16, __nv_bfloat16, wmma::col_major> bh[2], bl[2];
#pragma unroll
            for (int i = 0; i < 2; i++) {
                wmma::load_matrix_sync(ah[i], Abase + (i * 16) * LDA_S + ks, LDA_S);
                wmma::load_matrix_sync(al[i], Abase + (i * 16) * LDA_S + 32 + ks, LDA_S);
            }
#pragma unroll
            for (int j = 0; j < 2; j++) {
                wmma::load_matrix_sync(bh[j], Bbase + (j * 16) * LDA_S + ks, LDA_S);
                wmma::load_matrix_sync(bl[j], Bbase + (j * 16) * LDA_S + 32 + ks, LDA_S);
            }
#pragma unroll
            for (int i = 0; i < 2; i++)
#pragma unroll
                for (int j = 0; j < 2; j++) {
                    wmma::mma_sync(acc[i][j], ah[i], bh[j], acc[i][j]);
                    wmma::mma_sync(acc[i][j], ah[i], bl[j], acc[i][j]);
                    wmma::mma_sync(acc[i][j], al[i], bh[j], acc[i][j]);
                }
        }
    }

    // ---- epilogue: two 128x32 halves via smem, + bias/relu ----
    const int relu = flags & 1;
#pragma unroll
    for (int h = 0; h < 2; h++) {
        __syncthreads();
        if (warp_n == h) {
#pragma unroll
            for (int i = 0; i < 2; i++)
#pragma unroll
                for (int j = 0; j < 2; j++)
                    wmma::store_matrix_sync(
                        Cs + (warp_m * 32 + i * 16) * 36 + j * 16,
                        acc[i][j], 36, wmma::mem_row_major);
        }
        __syncthreads();
        int r = tid >> 1;
        int c0 = (tid & 1) * 16;
        float* crow = Cm + offC + (long long)(row0 + r) * ldc + n0 + h * 32;
#pragma unroll
        for (int q = 0; q < 4; q++) {
            int col = c0 + q * 4;
            float4 v = *(float4*)(Cs + r * 36 + col);
            v.x += biass[h * 32 + col + 0];
            v.y += biass[h * 32 + col + 1];
            v.z += biass[h * 32 + col + 2];
            v.w += biass[h * 32 + col + 3];
            if (relu) {
                v.x = fmaxf(v.x, 0.f); v.y = fmaxf(v.y, 0.f);
                v.z = fmaxf(v.z, 0.f); v.w = fmaxf(v.w, 0.f);
            }
            *(float4*)(crow + col) = v;
        }
    }
}

// ------------------------------- pooling ------------------------------------
__global__ void pool_kernel(const float* __restrict__ tokens,
                            const int* __restrict__ seg,
                            float* __restrict__ x) {
    int c = blockIdx.x;
    int b = blockIdx.y;
    const int* ids = seg + (size_t)b * S_;
    int lo = 0, hi = S_;
    while (lo < hi) { int mid = (lo + hi) >> 1; if (ids[mid] < c) lo = mid + 1; else hi = mid; }
    int s0 = lo;
    hi = S_;
    while (lo < hi) { int mid = (lo + hi) >> 1; if (ids[mid] < c + 1) lo = mid + 1; else hi = mid; }
    int s1 = lo;
    float inv = 1.0f / (float)(s1 - s0);

    int d = threadIdx.x;
    float sum0 = 0.f, sum1 = 0.f;
    for (int s = s0; s < s1; s++) {
        const float* t = tokens + ((size_t)b * S_ + s) * D_;
        sum0 += t[d];
        sum1 += t[d + 256];
    }
    float* xr = x + ((size_t)b * C_ + c) * D_;
    xr[d]       = sum0 * inv;
    xr[d + 256] = sum1 * inv;
}

// ------------------------------- softmax ------------------------------------
__global__ void softmax_kernel(float* __restrict__ s) {
    long long base = (long long)blockIdx.x * 512;
    int tid = threadIdx.x;             // 128
    int lane = tid & 31, warp = tid >> 5;
    float4 v = *(float4*)(s + base + tid * 4);
    v.x *= 0.125f; v.y *= 0.125f; v.z *= 0.125f; v.w *= 0.125f;

    __shared__ float red[4];
    float mx = fmaxf(fmaxf(v.x, v.y), fmaxf(v.z, v.w));
#pragma unroll
    for (int o = 16; o >= 1; o >>= 1) mx = fmaxf(mx, __shfl_xor_sync(0xffffffffu, mx, o));
    if (lane == 0) red[warp] = mx;
    __syncthreads();
    mx = fmaxf(fmaxf(red[0], red[1]), fmaxf(red[2], red[3]));

    float4 e;
    e.x = __expf(v.x - mx); e.y = __expf(v.y - mx);
    e.z = __expf(v.z - mx); e.w = __expf(v.w - mx);
    float sum = e.x + e.y + e.z + e.w;
#pragma unroll
    for (int o = 16; o >= 1; o >>= 1) sum += __shfl_xor_sync(0xffffffffu, sum, o);
    __syncthreads();
    if (lane == 0) red[warp] = sum;
    __syncthreads();
    float inv = 1.0f / (red[0] + red[1] + red[2] + red[3]);
    e.x *= inv; e.y *= inv; e.z *= inv; e.w *= inv;
    *(float4*)(s + base + tid * 4) = e;
}

// -------------------------- residual + layernorm ----------------------------
__global__ void ln_kernel(const float* __restrict__ xin,
                          const float* __restrict__ res,
                          const float* __restrict__ w,
                          const float* __restrict__ bv,
                          float* __restrict__ out) {
    int row = blockIdx.x;
    int tid = threadIdx.x;
    size_t off = (size_t)row * D_;
    float v0 = xin[off + tid];
    float v1 = xin[off + tid + 256];
    if (res) { v0 += res[off + tid]; v1 += res[off + tid + 256]; }

    __shared__ float red[8];
    __shared__ float sbc;
    int lane = tid & 31, warp = tid >> 5;

    float s = v0 + v1;
#pragma unroll
    for (int o2 = 16; o2 >= 1; o2 >>= 1) s += __shfl_xor_sync(0xffffffffu, s, o2);
    if (lane == 0) red[warp] = s;
    __syncthreads();
    if (tid == 0) {
        float t = 0.f;
#pragma unroll
        for (int i = 0; i < 8; i++) t += red[i];
        sbc = t * (1.0f / D_);
    }
    __syncthreads();
    float mu = sbc;
    float d0 = v0 - mu, d1 = v1 - mu;
    s = d0 * d0 + d1 * d1;
    __syncthreads();
#pragma unroll
    for (int o2 = 16; o2 >= 1; o2 >>= 1) s += __shfl_xor_sync(0xffffffffu, s, o2);
    if (lane == 0) red[warp] = s;
    __syncthreads();
    if (tid == 0) {
        float t = 0.f;
#pragma unroll
        for (int i = 0; i < 8; i++) t += red[i];
        sbc = rsqrtf(t * (1.0f / D_) + 1e-5f);
    }
    __syncthreads();
    float inv = sbc;
    out[off + tid]       = d0 * inv * w[tid] + bv[tid];
    out[off + tid + 256] = d1 * inv * w[tid + 256] + bv[tid + 256];
}

// ------------------------------- expand -------------------------------------
__global__ void expand_kernel(const float* __restrict__ y,
                              const int* __restrict__ seg,
                              float* __restrict__ out) {
    int bs = blockIdx.x;
    int b = bs >> 13;
    int c = seg[bs];
    const float4* src = (const float4*)(y + ((size_t)b * C_ + c) * D_);
    float4* dst = (float4*)(out + (size_t)bs * D_);
    dst[threadIdx.x] = src[threadIdx.x];
}

// ------------------------------ launcher ------------------------------------
extern "C" void kernel_launch(void* const* d_in, const int* in_sizes, int n_in,
                              void* d_out, int out_size) {
    const float* tokens = (const float*)d_in[0];
    const int*   seg    = (const int*)d_in[1];
    const float* qkv_w  = (const float*)d_in[2];
    const float* qkv_b  = (const float*)d_in[3];
    const float* out_w  = (const float*)d_in[4];
    const float* out_b  = (const float*)d_in[5];
    const float* ln1_w  = (const float*)d_in[6];
    const float* ln1_b  = (const float*)d_in[7];
    const float* ln2_w  = (const float*)d_in[8];
    const float* ln2_b  = (const float*)d_in[9];
    const float* ff1_w  = (const float*)d_in[10];
    const float* ff1_b  = (const float*)d_in[11];
    const float* ff2_w  = (const float*)d_in[12];
    const float* ff2_b  = (const float*)d_in[13];
    const float* fln_w  = (const float*)d_in[14];
    const float* fln_b  = (const float*)d_in[15];
    float* out = (float*)d_out;

    float *x, *qkv, *attno, *proj, *ff, *y, *scores;
    cudaGetSymbolAddress((void**)&x, g_x);
    cudaGetSymbolAddress((void**)&qkv, g_qkv);
    cudaGetSymbolAddress((void**)&attno, g_attno);
    cudaGetSymbolAddress((void**)&proj, g_proj);
    cudaGetSymbolAddress((void**)&ff, g_ff);
    cudaGetSymbolAddress((void**)&y, g_y);
    cudaGetSymbolAddress((void**)&scores, g_scores);

    pool_kernel<<<dim3(C_, B_), 256>>>(tokens, seg, x);

    const long long CC = (long long)C_ * C_;          // 262144
    const long long CQ = (long long)C_ * QKV3D;       // 786432

    for (int l = 0; l < L_; l++) {
        const float* qw = qkv_w + (size_t)l * QKV3D * D_;
        const float* qb = qkv_b + (size_t)l * QKV3D;
        const float* ow = out_w + (size_t)l * D_ * D_;
        const float* ob = out_b + (size_t)l * D_;
        const float* f1w = ff1_w + (size_t)l * DFF_ * D_;
        const float* f1b = ff1_b + (size_t)l * DFF_;
        const float* f2w = ff2_w + (size_t)l * D_ * DFF_;
        const float* f2b = ff2_b + (size_t)l * D_;

        // QKV: [4096,512] @ [1536,512]^T
        gemm_mma<<<dim3(QKV3D / 64, M_ / 128, 1), 256>>>(
            x, qw, qb, qkv, D_, D_, D_, QKV3D,
            0, 0, 0, 0, 0, 0, 0);

        // scores[b,h] = Q @ K^T  (64 batches, M=N=512, K=64)
        gemm_mma<<<dim3(C_ / 64, C_ / 128, B_ * H_), 256>>>(
            qkv, qkv + D_, nullptr, scores, HD_, QKV3D, QKV3D, C_,
            CQ, HD_, CQ, HD_, (long long)H_ * CC, CC, 0);

        softmax_kernel<<<B_ * H_ * C_, 128>>>(scores);

        // attno[b,:,h*64..] = P @ V  (64 batches, M=512, N=64, K=512; B is [K,N])
        gemm_mma<<<dim3(1, C_ / 128, B_ * H_), 256>>>(
            scores, qkv + 2 * D_, nullptr, attno, C_, C_, QKV3D, D_,
            (long long)H_ * CC, CC, CQ, HD_, (long long)C_ * D_, HD_, 2);

        // out proj
        gemm_mma<<<dim3(D_ / 64, M_ / 128, 1), 256>>>(
            attno, ow, ob, proj, D_, D_, D_, D_,
            0, 0, 0, 0, 0, 0, 0);
        ln_kernel<<<M_, 256>>>(x, proj, ln1_w + (size_t)l * D_, ln1_b + (size_t)l * D_, x);

        // ff1 (relu)
        gemm_mma<<<dim3(DFF_ / 64, M_ / 128, 1), 256>>>(
            x, f1w, f1b, ff, D_, D_, D_, DFF_,
            0, 0, 0, 0, 0, 0, 1);
        // ff2
        gemm_mma<<<dim3(D_ / 64, M_ / 128, 1), 256>>>(
            ff, f2w, f2b, proj, DFF_, DFF_, DFF_, D_,
            0, 0, 0, 0, 0, 0, 0);
        ln_kernel<<<M_, 256>>>(x, proj, ln2_w + (size_t)l * D_, ln2_b + (size_t)l * D_, x);
    }

    ln_kernel<<<M_, 256>>>(x, nullptr, fln_w, fln_b, y);
    expand_kernel<<<B_ * S_, 128>>>(y, seg, out);
}